// round 1
// baseline (speedup 1.0000x reference)
#include <cuda_runtime.h>
#include <math.h>

// sLSTM cell, fused: 8 GEMMs (x@W_g + h@U_g, g in {i,f,o,z}) + biases +
// gate nonlinearities + cell update, all in ONE kernel launch.
//
// Shapes: B=4096, D_IN=D_H=2048.
// Each block computes a 64(M) x 64(N) tile of ALL FOUR gate pre-activations
// (sharing the A tile across gates for 4x A-reuse), then does the elementwise
// epilogue in registers and writes h, c, n (concatenated in d_out).

#define BB 4096
#define DD 2048
#define TM 64
#define TN 64
#define TK 16
#define BD (BB * DD)   // 8388608 elements per output tensor

__global__ __launch_bounds__(256, 2)
void slstm_fused_kernel(
    const float* __restrict__ x,     const float* __restrict__ hprev,
    const float* __restrict__ cprev, const float* __restrict__ nprev,
    const float* __restrict__ Wi, const float* __restrict__ bi, const float* __restrict__ Ui,
    const float* __restrict__ Wf, const float* __restrict__ bf, const float* __restrict__ Uf,
    const float* __restrict__ Wo, const float* __restrict__ bo, const float* __restrict__ Uo,
    const float* __restrict__ Wz, const float* __restrict__ bz, const float* __restrict__ Uz,
    float* __restrict__ out)
{
    __shared__ float As[TK][TM];        // A tile, transposed (k-major)
    __shared__ float Bs[4][TK][TN];     // one B tile per gate

    const int tid = threadIdx.x;        // 256 threads = 16x16
    const int ty  = tid >> 4;           // 0..15 -> 4 M-rows each
    const int tx  = tid & 15;           // 0..15 -> 4 N-cols each
    const int m0  = blockIdx.y * TM;
    const int j0  = blockIdx.x * TN;

    // Loader indices
    const int ar = tid >> 2;            // 0..63  (M row within tile)
    const int ac = (tid & 3) * 4;       // 0,4,8,12 (k offset, float4)
    const int br = tid >> 4;            // 0..15  (k row within tile)
    const int bc = (tid & 15) * 4;      // 0..60  (j offset, float4)

    float acc[4][4][4];
    #pragma unroll
    for (int g = 0; g < 4; ++g)
        #pragma unroll
        for (int im = 0; im < 4; ++im)
            #pragma unroll
            for (int jj = 0; jj < 4; ++jj)
                acc[g][im][jj] = 0.0f;

    // Phase 0: A = x,      B = W_g   (K = 2048)
    // Phase 1: A = h_prev, B = U_g   (K = 2048)
    #pragma unroll 1
    for (int ph = 0; ph < 2; ++ph) {
        const float* Ag  = ph ? hprev : x;
        const float* Bm0 = ph ? Ui : Wi;
        const float* Bm1 = ph ? Uf : Wf;
        const float* Bm2 = ph ? Uo : Wo;
        const float* Bm3 = ph ? Uz : Wz;

        #pragma unroll 1
        for (int k0 = 0; k0 < DD; k0 += TK) {
            __syncthreads();   // previous compute done before overwrite

            // Load A tile (64 x 16), store transposed
            float4 av = *(const float4*)&Ag[(size_t)(m0 + ar) * DD + k0 + ac];
            As[ac + 0][ar] = av.x;
            As[ac + 1][ar] = av.y;
            As[ac + 2][ar] = av.z;
            As[ac + 3][ar] = av.w;

            // Load 4 B tiles (16 x 64 each), k-major direct
            *(float4*)&Bs[0][br][bc] = *(const float4*)&Bm0[(size_t)(k0 + br) * DD + j0 + bc];
            *(float4*)&Bs[1][br][bc] = *(const float4*)&Bm1[(size_t)(k0 + br) * DD + j0 + bc];
            *(float4*)&Bs[2][br][bc] = *(const float4*)&Bm2[(size_t)(k0 + br) * DD + j0 + bc];
            *(float4*)&Bs[3][br][bc] = *(const float4*)&Bm3[(size_t)(k0 + br) * DD + j0 + bc];

            __syncthreads();

            #pragma unroll
            for (int kk = 0; kk < TK; ++kk) {
                float a[4];
                *(float4*)a = *(const float4*)&As[kk][ty * 4];
                #pragma unroll
                for (int g = 0; g < 4; ++g) {
                    float b[4];
                    *(float4*)b = *(const float4*)&Bs[g][kk][tx * 4];
                    #pragma unroll
                    for (int im = 0; im < 4; ++im)
                        #pragma unroll
                        for (int jj = 0; jj < 4; ++jj)
                            acc[g][im][jj] = fmaf(a[im], b[jj], acc[g][im][jj]);
                }
            }
        }
    }

    // ---- Epilogue: biases + nonlinearities + cell update ----
    float bib[4], bfb[4], bob[4], bzb[4];
    #pragma unroll
    for (int jj = 0; jj < 4; ++jj) {
        int j = j0 + tx * 4 + jj;
        bib[jj] = bi[j];
        bfb[jj] = bf[j];
        bob[jj] = bo[j];
        bzb[jj] = bz[j];
    }

    #pragma unroll
    for (int im = 0; im < 4; ++im) {
        const int m = m0 + ty * 4 + im;
        #pragma unroll
        for (int jj = 0; jj < 4; ++jj) {
            const int j = j0 + tx * 4 + jj;
            const size_t idx = (size_t)m * DD + j;

            float pi = acc[0][im][jj] + bib[jj];
            float pf = acc[1][im][jj] + bfb[jj];
            float po = acc[2][im][jj] + bob[jj];
            float pz = acc[3][im][jj] + bzb[jj];

            float ig = expf(pi);
            float fg = expf(pf);
            float og = 1.0f / (1.0f + expf(-po));
            float zg = tanhf(pz);

            float cv = fg * cprev[idx] + ig * zg;
            float nv = fg * nprev[idx] + ig;
            float hv = og * (cv / (nv + 1e-6f));

            out[idx]            = hv;   // h
            out[BD + idx]       = cv;   // c
            out[2 * (size_t)BD + idx] = nv;   // n
        }
    }
}

extern "C" void kernel_launch(void* const* d_in, const int* in_sizes, int n_in,
                              void* d_out, int out_size)
{
    const float* x     = (const float*)d_in[0];
    const float* hprev = (const float*)d_in[1];
    const float* cprev = (const float*)d_in[2];
    const float* nprev = (const float*)d_in[3];
    const float* Wi = (const float*)d_in[4];
    const float* bi = (const float*)d_in[5];
    const float* Ui = (const float*)d_in[6];
    const float* Wf = (const float*)d_in[7];
    const float* bf = (const float*)d_in[8];
    const float* Uf = (const float*)d_in[9];
    const float* Wo = (const float*)d_in[10];
    const float* bo = (const float*)d_in[11];
    const float* Uo = (const float*)d_in[12];
    const float* Wz = (const float*)d_in[13];
    const float* bz = (const float*)d_in[14];
    const float* Uz = (const float*)d_in[15];
    float* out = (float*)d_out;

    dim3 grid(DD / TN, BB / TM);   // (32, 64)
    dim3 block(256);
    slstm_fused_kernel<<<grid, block>>>(
        x, hprev, cprev, nprev,
        Wi, bi, Ui, Wf, bf, Uf, Wo, bo, Uo, Wz, bz, Uz,
        out);
}

// round 2
// speedup vs baseline: 1.0008x; 1.0008x over previous
#include <cuda_runtime.h>
#include <math.h>

// sLSTM cell, fused: 8 GEMMs (x@W_g + h@U_g, g in {i,f,o,z}) + biases +
// gate nonlinearities + cell update, all in ONE kernel launch.
//
// Shapes: B=4096, D_IN=D_H=2048.
// Each block computes a 64(M) x 64(N) tile of ALL FOUR gate pre-activations
// (sharing the A tile across gates for 4x A-reuse), then does the elementwise
// epilogue in registers and writes h, c, n (concatenated in d_out).

#define BB 4096
#define DD 2048
#define TM 64
#define TN 64
#define TK 16
#define BD (BB * DD)   // 8388608 elements per output tensor

__global__ __launch_bounds__(256, 2)
void slstm_fused_kernel(
    const float* __restrict__ x,     const float* __restrict__ hprev,
    const float* __restrict__ cprev, const float* __restrict__ nprev,
    const float* __restrict__ Wi, const float* __restrict__ bi, const float* __restrict__ Ui,
    const float* __restrict__ Wf, const float* __restrict__ bf, const float* __restrict__ Uf,
    const float* __restrict__ Wo, const float* __restrict__ bo, const float* __restrict__ Uo,
    const float* __restrict__ Wz, const float* __restrict__ bz, const float* __restrict__ Uz,
    float* __restrict__ out)
{
    __shared__ float As[TK][TM];        // A tile, transposed (k-major)
    __shared__ float Bs[4][TK][TN];     // one B tile per gate

    const int tid = threadIdx.x;        // 256 threads = 16x16
    const int ty  = tid >> 4;           // 0..15 -> 4 M-rows each
    const int tx  = tid & 15;           // 0..15 -> 4 N-cols each
    const int m0  = blockIdx.y * TM;
    const int j0  = blockIdx.x * TN;

    // Loader indices
    const int ar = tid >> 2;            // 0..63  (M row within tile)
    const int ac = (tid & 3) * 4;       // 0,4,8,12 (k offset, float4)
    const int br = tid >> 4;            // 0..15  (k row within tile)
    const int bc = (tid & 15) * 4;      // 0..60  (j offset, float4)

    float acc[4][4][4];
    #pragma unroll
    for (int g = 0; g < 4; ++g)
        #pragma unroll
        for (int im = 0; im < 4; ++im)
            #pragma unroll
            for (int jj = 0; jj < 4; ++jj)
                acc[g][im][jj] = 0.0f;

    // Phase 0: A = x,      B = W_g   (K = 2048)
    // Phase 1: A = h_prev, B = U_g   (K = 2048)
    #pragma unroll 1
    for (int ph = 0; ph < 2; ++ph) {
        const float* Ag  = ph ? hprev : x;
        const float* Bm0 = ph ? Ui : Wi;
        const float* Bm1 = ph ? Uf : Wf;
        const float* Bm2 = ph ? Uo : Wo;
        const float* Bm3 = ph ? Uz : Wz;

        #pragma unroll 1
        for (int k0 = 0; k0 < DD; k0 += TK) {
            __syncthreads();   // previous compute done before overwrite

            // Load A tile (64 x 16), store transposed
            float4 av = *(const float4*)&Ag[(size_t)(m0 + ar) * DD + k0 + ac];
            As[ac + 0][ar] = av.x;
            As[ac + 1][ar] = av.y;
            As[ac + 2][ar] = av.z;
            As[ac + 3][ar] = av.w;

            // Load 4 B tiles (16 x 64 each), k-major direct
            *(float4*)&Bs[0][br][bc] = *(const float4*)&Bm0[(size_t)(k0 + br) * DD + j0 + bc];
            *(float4*)&Bs[1][br][bc] = *(const float4*)&Bm1[(size_t)(k0 + br) * DD + j0 + bc];
            *(float4*)&Bs[2][br][bc] = *(const float4*)&Bm2[(size_t)(k0 + br) * DD + j0 + bc];
            *(float4*)&Bs[3][br][bc] = *(const float4*)&Bm3[(size_t)(k0 + br) * DD + j0 + bc];

            __syncthreads();

            #pragma unroll
            for (int kk = 0; kk < TK; ++kk) {
                float a[4];
                *(float4*)a = *(const float4*)&As[kk][ty * 4];
                #pragma unroll
                for (int g = 0; g < 4; ++g) {
                    float b[4];
                    *(float4*)b = *(const float4*)&Bs[g][kk][tx * 4];
                    #pragma unroll
                    for (int im = 0; im < 4; ++im)
                        #pragma unroll
                        for (int jj = 0; jj < 4; ++jj)
                            acc[g][im][jj] = fmaf(a[im], b[jj], acc[g][im][jj]);
                }
            }
        }
    }

    // ---- Epilogue: biases + nonlinearities + cell update ----
    float bib[4], bfb[4], bob[4], bzb[4];
    #pragma unroll
    for (int jj = 0; jj < 4; ++jj) {
        int j = j0 + tx * 4 + jj;
        bib[jj] = bi[j];
        bfb[jj] = bf[j];
        bob[jj] = bo[j];
        bzb[jj] = bz[j];
    }

    #pragma unroll
    for (int im = 0; im < 4; ++im) {
        const int m = m0 + ty * 4 + im;
        #pragma unroll
        for (int jj = 0; jj < 4; ++jj) {
            const int j = j0 + tx * 4 + jj;
            const size_t idx = (size_t)m * DD + j;

            float pi = acc[0][im][jj] + bib[jj];
            float pf = acc[1][im][jj] + bfb[jj];
            float po = acc[2][im][jj] + bob[jj];
            float pz = acc[3][im][jj] + bzb[jj];

            float ig = expf(pi);
            float fg = expf(pf);
            float og = 1.0f / (1.0f + expf(-po));
            float zg = tanhf(pz);

            float cv = fg * cprev[idx] + ig * zg;
            float nv = fg * nprev[idx] + ig;
            float hv = og * (cv / (nv + 1e-6f));

            out[idx]            = hv;   // h
            out[BD + idx]       = cv;   // c
            out[2 * (size_t)BD + idx] = nv;   // n
        }
    }
}

extern "C" void kernel_launch(void* const* d_in, const int* in_sizes, int n_in,
                              void* d_out, int out_size)
{
    const float* x     = (const float*)d_in[0];
    const float* hprev = (const float*)d_in[1];
    const float* cprev = (const float*)d_in[2];
    const float* nprev = (const float*)d_in[3];
    const float* Wi = (const float*)d_in[4];
    const float* bi = (const float*)d_in[5];
    const float* Ui = (const float*)d_in[6];
    const float* Wf = (const float*)d_in[7];
    const float* bf = (const float*)d_in[8];
    const float* Uf = (const float*)d_in[9];
    const float* Wo = (const float*)d_in[10];
    const float* bo = (const float*)d_in[11];
    const float* Uo = (const float*)d_in[12];
    const float* Wz = (const float*)d_in[13];
    const float* bz = (const float*)d_in[14];
    const float* Uz = (const float*)d_in[15];
    float* out = (float*)d_out;

    dim3 grid(DD / TN, BB / TM);   // (32, 64)
    dim3 block(256);
    slstm_fused_kernel<<<grid, block>>>(
        x, hprev, cprev, nprev,
        Wi, bi, Ui, Wf, bf, Uf, Wo, bo, Uo, Wz, bz, Uz,
        out);
}